// round 12
// baseline (speedup 1.0000x reference)
#include <cuda_runtime.h>
#include <cuda_fp16.h>
#include <cstdint>

// GraphConvLayer via CSR keyed by (dst*5+type), type-contiguous segments,
// fold-at-boundary, fp16 gather payload (fp32 accumulation).
// This round: ILP-8 hist/scatter, convert fused into scatter launch
// (off critical path), prefetch depth 8 in main.

#define NTYPES 5
#define MAXE   1700000
#define MAXN   50001
#define MAXB   (MAXN * NTYPES)
#define SCAN_BS 1024
#define SCAN_ITEMS 4
#define SCAN_TILE (SCAN_BS * SCAN_ITEMS)

__device__ __half g_xh[(size_t)MAXN * 128];
__device__ int g_cnt[MAXB];
__device__ int g_off[MAXB + 1];
__device__ int g_rank[MAXE];
__device__ int g_bin[MAXE];
__device__ int g_packed[MAXE];
__device__ unsigned int g_state[128];

// ---------------- histogram: 8 edges/thread, rank capture ----------------

__global__ void hist_kernel(const int* __restrict__ dst,
                            const int* __restrict__ et, int E) {
    if (blockIdx.x == 0 && threadIdx.x < 128) g_state[threadIdx.x] = 0;
    const int i = blockIdx.x * blockDim.x + threadIdx.x;
    const int e = i * 8;
    if (e + 7 < E) {
        int4 d0 = ((const int4*)dst)[2 * i];
        int4 d1 = ((const int4*)dst)[2 * i + 1];
        int4 t0 = ((const int4*)et)[2 * i];
        int4 t1 = ((const int4*)et)[2 * i + 1];
        int b[8];
        b[0] = d0.x * NTYPES + t0.x - 1;  b[1] = d0.y * NTYPES + t0.y - 1;
        b[2] = d0.z * NTYPES + t0.z - 1;  b[3] = d0.w * NTYPES + t0.w - 1;
        b[4] = d1.x * NTYPES + t1.x - 1;  b[5] = d1.y * NTYPES + t1.y - 1;
        b[6] = d1.z * NTYPES + t1.z - 1;  b[7] = d1.w * NTYPES + t1.w - 1;
        int r[8];
        #pragma unroll
        for (int q = 0; q < 8; q++) r[q] = atomicAdd(&g_cnt[b[q]], 1);
        ((int4*)g_bin)[2 * i]      = make_int4(b[0], b[1], b[2], b[3]);
        ((int4*)g_bin)[2 * i + 1]  = make_int4(b[4], b[5], b[6], b[7]);
        ((int4*)g_rank)[2 * i]     = make_int4(r[0], r[1], r[2], r[3]);
        ((int4*)g_rank)[2 * i + 1] = make_int4(r[4], r[5], r[6], r[7]);
    } else {
        for (int k = e; k < E; k++) {
            int bin = dst[k] * NTYPES + (et[k] - 1);
            g_bin[k]  = bin;
            g_rank[k] = atomicAdd(&g_cnt[bin], 1);
        }
    }
}

// ---------------- single-pass scan (decoupled lookback) ----------------

__device__ __forceinline__ int block_exscan_1024(int v, int* wtot) {
    const int lane = threadIdx.x & 31, w = threadIdx.x >> 5;
    int xv = v;
    #pragma unroll
    for (int s = 1; s < 32; s <<= 1) {
        int y = __shfl_up_sync(0xffffffffu, xv, s);
        if (lane >= s) xv += y;
    }
    if (lane == 31) wtot[w] = xv;
    __syncthreads();
    if (w == 0) {
        int y = wtot[lane];
        #pragma unroll
        for (int s = 1; s < 32; s <<= 1) {
            int z = __shfl_up_sync(0xffffffffu, y, s);
            if (lane >= s) y += z;
        }
        wtot[lane] = y;
    }
    __syncthreads();
    return xv - v + ((w > 0) ? wtot[w - 1] : 0);
}

__global__ void __launch_bounds__(SCAN_BS) scan_lookback(int B, int E) {
    __shared__ int wtot[32];
    __shared__ int s_prev;
    const int bid = blockIdx.x, tid = threadIdx.x;
    const int base = bid * SCAN_TILE + tid * SCAN_ITEMS;

    int4 v = make_int4(0, 0, 0, 0);
    if (base + 3 < B) v = *(const int4*)&g_cnt[base];
    else {
        if (base     < B) v.x = g_cnt[base];
        if (base + 1 < B) v.y = g_cnt[base + 1];
        if (base + 2 < B) v.z = g_cnt[base + 2];
        if (base + 3 < B) v.w = g_cnt[base + 3];
    }
    const int s = v.x + v.y + v.z + v.w;
    const int ex = block_exscan_1024(s, wtot);

    if (tid == SCAN_BS - 1) {
        const int btot = ex + s;
        if (bid == 0) {
            atomicExch(&g_state[0], (2u << 30) | (unsigned)btot);
            s_prev = 0;
        } else {
            atomicExch(&g_state[bid], (1u << 30) | (unsigned)btot);
            int prev = 0;
            for (int j = bid - 1; ; j--) {
                unsigned w;
                do { w = atomicOr(&g_state[j], 0u); } while ((w >> 30) == 0u);
                prev += (int)(w & 0x3FFFFFFFu);
                if ((w >> 30) == 2u) break;
            }
            atomicExch(&g_state[bid], (2u << 30) | (unsigned)(prev + btot));
            s_prev = prev;
        }
    }
    __syncthreads();

    const int off0 = s_prev + ex;
    if (base < B) {
        g_off[base] = off0;
        if (base + 1 < B) g_off[base + 1] = off0 + v.x;
        if (base + 2 < B) g_off[base + 2] = off0 + v.x + v.y;
        if (base + 3 < B) g_off[base + 3] = off0 + v.x + v.y + v.z;
    }
    if (bid == 0 && tid == 0) g_off[B] = E;
}

// ------- fused: scatter (8 edges/thread, atomic-free) || convert x->fp16 -------

__global__ void scatcvt_kernel(const int* __restrict__ src,
                               const float* __restrict__ x,
                               int E, int nF4, int sblocks) {
    if ((int)blockIdx.x < sblocks) {
        const int i = blockIdx.x * blockDim.x + threadIdx.x;
        const int e = i * 8;
        if (e + 7 < E) {
            int4 s0 = ((const int4*)src)[2 * i];
            int4 s1 = ((const int4*)src)[2 * i + 1];
            int4 b0 = ((const int4*)g_bin)[2 * i];
            int4 b1 = ((const int4*)g_bin)[2 * i + 1];
            int4 r0 = ((const int4*)g_rank)[2 * i];
            int4 r1 = ((const int4*)g_rank)[2 * i + 1];
            int p[8];   // 8 independent random gathers -> MLP 8
            p[0] = g_off[b0.x] + r0.x;  p[1] = g_off[b0.y] + r0.y;
            p[2] = g_off[b0.z] + r0.z;  p[3] = g_off[b0.w] + r0.w;
            p[4] = g_off[b1.x] + r1.x;  p[5] = g_off[b1.y] + r1.y;
            p[6] = g_off[b1.z] + r1.z;  p[7] = g_off[b1.w] + r1.w;
            g_packed[p[0]] = s0.x;  g_packed[p[1]] = s0.y;
            g_packed[p[2]] = s0.z;  g_packed[p[3]] = s0.w;
            g_packed[p[4]] = s1.x;  g_packed[p[5]] = s1.y;
            g_packed[p[6]] = s1.z;  g_packed[p[7]] = s1.w;
        } else {
            for (int k = e; k < E; k++)
                g_packed[g_off[g_bin[k]] + g_rank[k]] = src[k];
        }
    } else {
        const int i = (blockIdx.x - sblocks) * blockDim.x + threadIdx.x;
        if (i < nF4) {
            float4 v = ((const float4*)x)[i];
            __half2 h0 = __floats2half2_rn(v.x, v.y);
            __half2 h1 = __floats2half2_rn(v.z, v.w);
            uint2 u;
            u.x = *reinterpret_cast<unsigned*>(&h0);
            u.y = *reinterpret_cast<unsigned*>(&h1);
            ((uint2*)g_xh)[i] = u;
        }
    }
}

// ------- main: warp per node, fp16 gather, fp32 accumulate, prefetch 8 -------

__global__ void __launch_bounds__(256, 3)
gcl_main(const float* __restrict__ W,
         const float* __restrict__ Bv,
         float* __restrict__ out, int N)
{
    __shared__ float Wsh[NTYPES][8][8];
    __shared__ float Bsh[NTYPES][8];
    __shared__ float aggS[8][8][16];

    const int tid = threadIdx.x;
    for (int i = tid; i < NTYPES * 64; i += 256) {
        int t = i >> 6, rem = i & 63;
        Wsh[t][rem >> 3][rem & 7] = W[i];
    }
    for (int i = tid; i < NTYPES * 8; i += 256) Bsh[i >> 3][i & 7] = Bv[i];
    __syncthreads();

    const int lane = tid & 31, wl = tid >> 5;
    const int n = blockIdx.x * 8 + wl;
    if (n >= N) return;

    const int myBnd = g_off[n * NTYPES + ((lane < NTYPES + 1) ? lane : NTYPES)];
    const int beg = __shfl_sync(0xffffffffu, myBnd, 0);
    const int end = __shfl_sync(0xffffffffu, myBnd, NTYPES);

    const int o  = lane >> 2;
    const int cg = lane & 3;

    float a0 = 0.f, a1 = 0.f, a2 = 0.f, a3 = 0.f;
    float ax = 0.f, ay = 0.f, az = 0.f, aw = 0.f;

    int tcur = 0;
    int nextB = __shfl_sync(0xffffffffu, myBnd, 1);

    const uint2* __restrict__ xh = (const uint2*)g_xh;

    for (int base = beg; base < end; base += 32) {
        const int j32 = base + lane;
        const int pk = (j32 < end) ? g_packed[j32] : 0;
        int m = end - base; if (m > 32) m = 32;

        uint2 v[8];
        #pragma unroll
        for (int q = 0; q < 8; q++) {
            int idx = (q < m) ? q : (m - 1);
            int s = __shfl_sync(0xffffffffu, pk, idx);
            v[q] = xh[(size_t)s * 32 + lane];
        }

        for (int k0 = 0; k0 < m; k0 += 8) {
            uint2 c[8];
            #pragma unroll
            for (int q = 0; q < 8; q++) c[q] = v[q];
            if (k0 + 8 < m) {
                #pragma unroll
                for (int q = 0; q < 8; q++) {
                    int kk = k0 + 8 + q;
                    int idx = (kk < m) ? kk : (m - 1);
                    int s = __shfl_sync(0xffffffffu, pk, idx);
                    v[q] = xh[(size_t)s * 32 + lane];
                }
            }
            #pragma unroll
            for (int q = 0; q < 8; q++) {
                const int k = k0 + q;
                if (k < m) {
                    const int j = base + k;
                    while (j >= nextB) {   // warp-uniform type-boundary fold
                        *(float4*)(&aggS[wl][o][cg * 4]) =
                            make_float4(a0, a1, a2, a3);
                        __syncwarp();
                        #pragma unroll
                        for (int i = 0; i < 8; i++) {
                            const float wv = Wsh[tcur][o][i];
                            const float4 a = *(const float4*)(&aggS[wl][i][cg * 4]);
                            ax += wv * a.x; ay += wv * a.y;
                            az += wv * a.z; aw += wv * a.w;
                        }
                        __syncwarp();
                        a0 = a1 = a2 = a3 = 0.f;
                        tcur++;
                        nextB = __shfl_sync(0xffffffffu, myBnd,
                                            (tcur < NTYPES) ? (tcur + 1) : NTYPES);
                    }
                    __half2 h0 = *reinterpret_cast<const __half2*>(&c[q].x);
                    __half2 h1 = *reinterpret_cast<const __half2*>(&c[q].y);
                    float2 f0 = __half22float2(h0);
                    float2 f1 = __half22float2(h1);
                    a0 += f0.x; a1 += f0.y; a2 += f1.x; a3 += f1.y;
                }
            }
        }
    }

    // final fold
    *(float4*)(&aggS[wl][o][cg * 4]) = make_float4(a0, a1, a2, a3);
    __syncwarp();
    #pragma unroll
    for (int i = 0; i < 8; i++) {
        const float wv = Wsh[tcur][o][i];
        const float4 a = *(const float4*)(&aggS[wl][i][cg * 4]);
        ax += wv * a.x; ay += wv * a.y; az += wv * a.z; aw += wv * a.w;
    }

    float bias = 0.f;
    #pragma unroll
    for (int t = 0; t < NTYPES; t++) {
        int lo = __shfl_sync(0xffffffffu, myBnd, t);
        int hi = __shfl_sync(0xffffffffu, myBnd, t + 1);
        bias += (float)(hi - lo) * Bsh[t][o];
    }

    float4 res = { ax + bias, ay + bias, az + bias, aw + bias };
    *(float4*)(out + (size_t)n * 128 + o * 16 + cg * 4) = res;
}

// ---------------- launch ----------------

extern "C" void kernel_launch(void* const* d_in, const int* in_sizes, int n_in,
                              void* d_out, int out_size)
{
    const float* x   = (const float*)d_in[0];
    const float* W   = (const float*)d_in[1];
    const float* Bv  = (const float*)d_in[2];
    const int*   src = (const int*)  d_in[3];
    const int*   dst = (const int*)  d_in[4];
    const int*   et  = (const int*)  d_in[5];
    float*       out = (float*)d_out;

    const int E = in_sizes[3];
    const int N = in_sizes[0] / 128;
    const int B = N * NTYPES;
    const int nF4 = N * 32;

    void* cnt_ptr = nullptr;
    cudaGetSymbolAddress(&cnt_ptr, g_cnt);
    cudaMemsetAsync(cnt_ptr, 0, (size_t)B * sizeof(int));

    const int tb = 256;
    const int e8blk = ((E + 7) / 8 + tb - 1) / tb;

    hist_kernel<<<e8blk, tb>>>(dst, et, E);

    scan_lookback<<<(B + SCAN_TILE - 1) / SCAN_TILE, SCAN_BS>>>(B, E);

    const int cblk = (nF4 + tb - 1) / tb;
    scatcvt_kernel<<<e8blk + cblk, tb>>>(src, x, E, nF4, e8blk);

    gcl_main<<<(N + 7) / 8, 256>>>(W, Bv, out, N);
}

// round 13
// speedup vs baseline: 1.0041x; 1.0041x over previous
#include <cuda_runtime.h>
#include <cstdint>

// GraphConvLayer via CSR keyed by (dst*5+type), type-contiguous segments.
// This round: fp32 gather from x (no convert), per-type segment loops
// (no per-edge boundary checks), uniform-load edge indices (no shfl),
// depth-4 pipeline, f32x2 accumulation. ILP-8 hist/scatter, lookback scan.

#define NTYPES 5
#define MAXE   1700000
#define MAXN   50001
#define MAXB   (MAXN * NTYPES)
#define SCAN_BS 1024
#define SCAN_ITEMS 4
#define SCAN_TILE (SCAN_BS * SCAN_ITEMS)

__device__ int g_cnt[MAXB];
__device__ int g_off[MAXB + 1];
__device__ int g_rank[MAXE];
__device__ int g_bin[MAXE];
__device__ int g_packed[MAXE];
__device__ unsigned int g_state[128];

// ---------------- histogram: 8 edges/thread, rank capture ----------------

__global__ void hist_kernel(const int* __restrict__ dst,
                            const int* __restrict__ et, int E) {
    if (blockIdx.x == 0 && threadIdx.x < 128) g_state[threadIdx.x] = 0;
    const int i = blockIdx.x * blockDim.x + threadIdx.x;
    const int e = i * 8;
    if (e + 7 < E) {
        int4 d0 = ((const int4*)dst)[2 * i];
        int4 d1 = ((const int4*)dst)[2 * i + 1];
        int4 t0 = ((const int4*)et)[2 * i];
        int4 t1 = ((const int4*)et)[2 * i + 1];
        int b[8];
        b[0] = d0.x * NTYPES + t0.x - 1;  b[1] = d0.y * NTYPES + t0.y - 1;
        b[2] = d0.z * NTYPES + t0.z - 1;  b[3] = d0.w * NTYPES + t0.w - 1;
        b[4] = d1.x * NTYPES + t1.x - 1;  b[5] = d1.y * NTYPES + t1.y - 1;
        b[6] = d1.z * NTYPES + t1.z - 1;  b[7] = d1.w * NTYPES + t1.w - 1;
        int r[8];
        #pragma unroll
        for (int q = 0; q < 8; q++) r[q] = atomicAdd(&g_cnt[b[q]], 1);
        ((int4*)g_bin)[2 * i]      = make_int4(b[0], b[1], b[2], b[3]);
        ((int4*)g_bin)[2 * i + 1]  = make_int4(b[4], b[5], b[6], b[7]);
        ((int4*)g_rank)[2 * i]     = make_int4(r[0], r[1], r[2], r[3]);
        ((int4*)g_rank)[2 * i + 1] = make_int4(r[4], r[5], r[6], r[7]);
    } else {
        for (int k = e; k < E; k++) {
            int bin = dst[k] * NTYPES + (et[k] - 1);
            g_bin[k]  = bin;
            g_rank[k] = atomicAdd(&g_cnt[bin], 1);
        }
    }
}

// ---------------- single-pass scan (decoupled lookback) ----------------

__device__ __forceinline__ int block_exscan_1024(int v, int* wtot) {
    const int lane = threadIdx.x & 31, w = threadIdx.x >> 5;
    int xv = v;
    #pragma unroll
    for (int s = 1; s < 32; s <<= 1) {
        int y = __shfl_up_sync(0xffffffffu, xv, s);
        if (lane >= s) xv += y;
    }
    if (lane == 31) wtot[w] = xv;
    __syncthreads();
    if (w == 0) {
        int y = wtot[lane];
        #pragma unroll
        for (int s = 1; s < 32; s <<= 1) {
            int z = __shfl_up_sync(0xffffffffu, y, s);
            if (lane >= s) y += z;
        }
        wtot[lane] = y;
    }
    __syncthreads();
    return xv - v + ((w > 0) ? wtot[w - 1] : 0);
}

__global__ void __launch_bounds__(SCAN_BS) scan_lookback(int B, int E) {
    __shared__ int wtot[32];
    __shared__ int s_prev;
    const int bid = blockIdx.x, tid = threadIdx.x;
    const int base = bid * SCAN_TILE + tid * SCAN_ITEMS;

    int4 v = make_int4(0, 0, 0, 0);
    if (base + 3 < B) v = *(const int4*)&g_cnt[base];
    else {
        if (base     < B) v.x = g_cnt[base];
        if (base + 1 < B) v.y = g_cnt[base + 1];
        if (base + 2 < B) v.z = g_cnt[base + 2];
        if (base + 3 < B) v.w = g_cnt[base + 3];
    }
    const int s = v.x + v.y + v.z + v.w;
    const int ex = block_exscan_1024(s, wtot);

    if (tid == SCAN_BS - 1) {
        const int btot = ex + s;
        if (bid == 0) {
            atomicExch(&g_state[0], (2u << 30) | (unsigned)btot);
            s_prev = 0;
        } else {
            atomicExch(&g_state[bid], (1u << 30) | (unsigned)btot);
            int prev = 0;
            for (int j = bid - 1; ; j--) {
                unsigned w;
                do { w = atomicOr(&g_state[j], 0u); } while ((w >> 30) == 0u);
                prev += (int)(w & 0x3FFFFFFFu);
                if ((w >> 30) == 2u) break;
            }
            atomicExch(&g_state[bid], (2u << 30) | (unsigned)(prev + btot));
            s_prev = prev;
        }
    }
    __syncthreads();

    const int off0 = s_prev + ex;
    if (base < B) {
        g_off[base] = off0;
        if (base + 1 < B) g_off[base + 1] = off0 + v.x;
        if (base + 2 < B) g_off[base + 2] = off0 + v.x + v.y;
        if (base + 3 < B) g_off[base + 3] = off0 + v.x + v.y + v.z;
    }
    if (bid == 0 && tid == 0) g_off[B] = E;
}

// ---------------- scatter: 8 edges/thread, atomic-free ----------------

__global__ void scatter_kernel(const int* __restrict__ src, int E) {
    const int i = blockIdx.x * blockDim.x + threadIdx.x;
    const int e = i * 8;
    if (e + 7 < E) {
        int4 s0 = ((const int4*)src)[2 * i];
        int4 s1 = ((const int4*)src)[2 * i + 1];
        int4 b0 = ((const int4*)g_bin)[2 * i];
        int4 b1 = ((const int4*)g_bin)[2 * i + 1];
        int4 r0 = ((const int4*)g_rank)[2 * i];
        int4 r1 = ((const int4*)g_rank)[2 * i + 1];
        int p[8];
        p[0] = g_off[b0.x] + r0.x;  p[1] = g_off[b0.y] + r0.y;
        p[2] = g_off[b0.z] + r0.z;  p[3] = g_off[b0.w] + r0.w;
        p[4] = g_off[b1.x] + r1.x;  p[5] = g_off[b1.y] + r1.y;
        p[6] = g_off[b1.z] + r1.z;  p[7] = g_off[b1.w] + r1.w;
        g_packed[p[0]] = s0.x;  g_packed[p[1]] = s0.y;
        g_packed[p[2]] = s0.z;  g_packed[p[3]] = s0.w;
        g_packed[p[4]] = s1.x;  g_packed[p[5]] = s1.y;
        g_packed[p[6]] = s1.z;  g_packed[p[7]] = s1.w;
    } else {
        for (int k = e; k < E; k++)
            g_packed[g_off[g_bin[k]] + g_rank[k]] = src[k];
    }
}

// ------- main: warp per node, per-type segment loops, depth-4 pipeline -------

__global__ void __launch_bounds__(256)
gcl_main(const float* __restrict__ x,
         const float* __restrict__ W,
         const float* __restrict__ Bv,
         float* __restrict__ out, int N)
{
    __shared__ float Wsh[NTYPES][8][8];
    __shared__ float Bsh[NTYPES][8];
    __shared__ float aggS[8][8][16];

    const int tid = threadIdx.x;
    for (int i = tid; i < NTYPES * 64; i += 256) {
        int t = i >> 6, rem = i & 63;
        Wsh[t][rem >> 3][rem & 7] = W[i];
    }
    for (int i = tid; i < NTYPES * 8; i += 256) Bsh[i >> 3][i & 7] = Bv[i];
    __syncthreads();

    const int lane = tid & 31, wl = tid >> 5;
    const int n = blockIdx.x * 8 + wl;
    if (n >= N) return;

    // warp-uniform segment boundaries (uniform loads -> L1 broadcast)
    int bnd[NTYPES + 1];
    #pragma unroll
    for (int t = 0; t <= NTYPES; t++) bnd[t] = g_off[n * NTYPES + t];

    const int o  = lane >> 2;
    const int cg = lane & 3;

    float ax = 0.f, ay = 0.f, az = 0.f, aw = 0.f;

    const ulonglong2* __restrict__ xq = (const ulonglong2*)x;

    #pragma unroll
    for (int t = 0; t < NTYPES; t++) {
        const int lo = bnd[t], hi = bnd[t + 1];
        if (lo == hi) continue;

        unsigned long long a01 = 0ull, a23 = 0ull;

        int j = lo;
        const int jend = hi - ((hi - lo) & 3);   // full groups of 4
        if (j < jend) {
            // prologue: group loads (4 uniform idx + 4 independent gathers)
            int s0 = g_packed[j],     s1 = g_packed[j + 1];
            int s2 = g_packed[j + 2], s3 = g_packed[j + 3];
            ulonglong2 v0 = xq[(s0 << 5) + lane];
            ulonglong2 v1 = xq[(s1 << 5) + lane];
            ulonglong2 v2 = xq[(s2 << 5) + lane];
            ulonglong2 v3 = xq[(s3 << 5) + lane];
            for (;;) {
                ulonglong2 c0 = v0, c1 = v1, c2 = v2, c3 = v3;
                j += 4;
                if (j < jend) {
                    s0 = g_packed[j];     s1 = g_packed[j + 1];
                    s2 = g_packed[j + 2]; s3 = g_packed[j + 3];
                    v0 = xq[(s0 << 5) + lane];
                    v1 = xq[(s1 << 5) + lane];
                    v2 = xq[(s2 << 5) + lane];
                    v3 = xq[(s3 << 5) + lane];
                }
                asm volatile("add.rn.f32x2 %0, %0, %2;\n\t"
                             "add.rn.f32x2 %1, %1, %3;"
                             : "+l"(a01), "+l"(a23) : "l"(c0.x), "l"(c0.y));
                asm volatile("add.rn.f32x2 %0, %0, %2;\n\t"
                             "add.rn.f32x2 %1, %1, %3;"
                             : "+l"(a01), "+l"(a23) : "l"(c1.x), "l"(c1.y));
                asm volatile("add.rn.f32x2 %0, %0, %2;\n\t"
                             "add.rn.f32x2 %1, %1, %3;"
                             : "+l"(a01), "+l"(a23) : "l"(c2.x), "l"(c2.y));
                asm volatile("add.rn.f32x2 %0, %0, %2;\n\t"
                             "add.rn.f32x2 %1, %1, %3;"
                             : "+l"(a01), "+l"(a23) : "l"(c3.x), "l"(c3.y));
                if (j >= jend) break;
            }
        }
        // remainder (<=3)
        for (; j < hi; j++) {
            int s = g_packed[j];
            ulonglong2 v = xq[(s << 5) + lane];
            asm volatile("add.rn.f32x2 %0, %0, %2;\n\t"
                         "add.rn.f32x2 %1, %1, %3;"
                         : "+l"(a01), "+l"(a23) : "l"(v.x), "l"(v.y));
        }

        // fold this type's aggregate through W[t] via shared transpose
        ulonglong2 u; u.x = a01; u.y = a23;
        *(ulonglong2*)(&aggS[wl][o][cg * 4]) = u;
        __syncwarp();
        #pragma unroll
        for (int i = 0; i < 8; i++) {
            const float wv = Wsh[t][o][i];
            const float4 a = *(const float4*)(&aggS[wl][i][cg * 4]);
            ax += wv * a.x; ay += wv * a.y; az += wv * a.z; aw += wv * a.w;
        }
        __syncwarp();
    }

    // bias from segment lengths
    float bias = 0.f;
    #pragma unroll
    for (int t = 0; t < NTYPES; t++)
        bias += (float)(bnd[t + 1] - bnd[t]) * Bsh[t][o];

    float4 res = { ax + bias, ay + bias, az + bias, aw + bias };
    *(float4*)(out + (size_t)n * 128 + o * 16 + cg * 4) = res;
}

// ---------------- launch ----------------

extern "C" void kernel_launch(void* const* d_in, const int* in_sizes, int n_in,
                              void* d_out, int out_size)
{
    const float* x   = (const float*)d_in[0];
    const float* W   = (const float*)d_in[1];
    const float* Bv  = (const float*)d_in[2];
    const int*   src = (const int*)  d_in[3];
    const int*   dst = (const int*)  d_in[4];
    const int*   et  = (const int*)  d_in[5];
    float*       out = (float*)d_out;

    const int E = in_sizes[3];
    const int N = in_sizes[0] / 128;
    const int B = N * NTYPES;

    void* cnt_ptr = nullptr;
    cudaGetSymbolAddress(&cnt_ptr, g_cnt);
    cudaMemsetAsync(cnt_ptr, 0, (size_t)B * sizeof(int));

    const int tb = 256;
    const int e8blk = ((E + 7) / 8 + tb - 1) / tb;

    hist_kernel<<<e8blk, tb>>>(dst, et, E);
    scan_lookback<<<(B + SCAN_TILE - 1) / SCAN_TILE, SCAN_BS>>>(B, E);
    scatter_kernel<<<e8blk, tb>>>(src, E);
    gcl_main<<<(N + 7) / 8, 256>>>(x, W, Bv, out, N);
}

// round 14
// speedup vs baseline: 1.0935x; 1.0890x over previous
#include <cuda_runtime.h>
#include <cuda_fp16.h>
#include <cstdint>

// GraphConvLayer via CSR keyed by (dst*5+type), type-contiguous segments.
// R14: fp16 gather payload (fp32 accumulation) + R13 clean segment-loop main
// (uniform index loads, depth-4 pipeline). Convert fused into hist launch.

#define NTYPES 5
#define MAXE   1700000
#define MAXN   50001
#define MAXB   (MAXN * NTYPES)
#define SCAN_BS 1024
#define SCAN_ITEMS 4
#define SCAN_TILE (SCAN_BS * SCAN_ITEMS)

__device__ __half g_xh[(size_t)MAXN * 128];
__device__ int g_cnt[MAXB];
__device__ int g_off[MAXB + 1];
__device__ int g_rank[MAXE];
__device__ int g_bin[MAXE];
__device__ int g_packed[MAXE];
__device__ unsigned int g_state[128];

// ------- fused: histogram (8 edges/thread, rank capture) || convert x->fp16 -------

__global__ void histcvt_kernel(const int* __restrict__ dst,
                               const int* __restrict__ et,
                               const float* __restrict__ x,
                               int E, int nF4, int hblocks) {
    if ((int)blockIdx.x < hblocks) {
        if (blockIdx.x == 0 && threadIdx.x < 128) g_state[threadIdx.x] = 0;
        const int i = blockIdx.x * blockDim.x + threadIdx.x;
        const int e = i * 8;
        if (e + 7 < E) {
            int4 d0 = ((const int4*)dst)[2 * i];
            int4 d1 = ((const int4*)dst)[2 * i + 1];
            int4 t0 = ((const int4*)et)[2 * i];
            int4 t1 = ((const int4*)et)[2 * i + 1];
            int b[8];
            b[0] = d0.x * NTYPES + t0.x - 1;  b[1] = d0.y * NTYPES + t0.y - 1;
            b[2] = d0.z * NTYPES + t0.z - 1;  b[3] = d0.w * NTYPES + t0.w - 1;
            b[4] = d1.x * NTYPES + t1.x - 1;  b[5] = d1.y * NTYPES + t1.y - 1;
            b[6] = d1.z * NTYPES + t1.z - 1;  b[7] = d1.w * NTYPES + t1.w - 1;
            int r[8];
            #pragma unroll
            for (int q = 0; q < 8; q++) r[q] = atomicAdd(&g_cnt[b[q]], 1);
            ((int4*)g_bin)[2 * i]      = make_int4(b[0], b[1], b[2], b[3]);
            ((int4*)g_bin)[2 * i + 1]  = make_int4(b[4], b[5], b[6], b[7]);
            ((int4*)g_rank)[2 * i]     = make_int4(r[0], r[1], r[2], r[3]);
            ((int4*)g_rank)[2 * i + 1] = make_int4(r[4], r[5], r[6], r[7]);
        } else {
            for (int k = e; k < E; k++) {
                int bin = dst[k] * NTYPES + (et[k] - 1);
                g_bin[k]  = bin;
                g_rank[k] = atomicAdd(&g_cnt[bin], 1);
            }
        }
    } else {
        const int i = (blockIdx.x - hblocks) * blockDim.x + threadIdx.x;
        if (i < nF4) {
            float4 v = ((const float4*)x)[i];
            __half2 h0 = __floats2half2_rn(v.x, v.y);
            __half2 h1 = __floats2half2_rn(v.z, v.w);
            uint2 u;
            u.x = *reinterpret_cast<unsigned*>(&h0);
            u.y = *reinterpret_cast<unsigned*>(&h1);
            ((uint2*)g_xh)[i] = u;
        }
    }
}

// ---------------- single-pass scan (decoupled lookback) ----------------

__device__ __forceinline__ int block_exscan_1024(int v, int* wtot) {
    const int lane = threadIdx.x & 31, w = threadIdx.x >> 5;
    int xv = v;
    #pragma unroll
    for (int s = 1; s < 32; s <<= 1) {
        int y = __shfl_up_sync(0xffffffffu, xv, s);
        if (lane >= s) xv += y;
    }
    if (lane == 31) wtot[w] = xv;
    __syncthreads();
    if (w == 0) {
        int y = wtot[lane];
        #pragma unroll
        for (int s = 1; s < 32; s <<= 1) {
            int z = __shfl_up_sync(0xffffffffu, y, s);
            if (lane >= s) y += z;
        }
        wtot[lane] = y;
    }
    __syncthreads();
    return xv - v + ((w > 0) ? wtot[w - 1] : 0);
}

__global__ void __launch_bounds__(SCAN_BS) scan_lookback(int B, int E) {
    __shared__ int wtot[32];
    __shared__ int s_prev;
    const int bid = blockIdx.x, tid = threadIdx.x;
    const int base = bid * SCAN_TILE + tid * SCAN_ITEMS;

    int4 v = make_int4(0, 0, 0, 0);
    if (base + 3 < B) v = *(const int4*)&g_cnt[base];
    else {
        if (base     < B) v.x = g_cnt[base];
        if (base + 1 < B) v.y = g_cnt[base + 1];
        if (base + 2 < B) v.z = g_cnt[base + 2];
        if (base + 3 < B) v.w = g_cnt[base + 3];
    }
    const int s = v.x + v.y + v.z + v.w;
    const int ex = block_exscan_1024(s, wtot);

    if (tid == SCAN_BS - 1) {
        const int btot = ex + s;
        if (bid == 0) {
            atomicExch(&g_state[0], (2u << 30) | (unsigned)btot);
            s_prev = 0;
        } else {
            atomicExch(&g_state[bid], (1u << 30) | (unsigned)btot);
            int prev = 0;
            for (int j = bid - 1; ; j--) {
                unsigned w;
                do { w = atomicOr(&g_state[j], 0u); } while ((w >> 30) == 0u);
                prev += (int)(w & 0x3FFFFFFFu);
                if ((w >> 30) == 2u) break;
            }
            atomicExch(&g_state[bid], (2u << 30) | (unsigned)(prev + btot));
            s_prev = prev;
        }
    }
    __syncthreads();

    const int off0 = s_prev + ex;
    if (base < B) {
        g_off[base] = off0;
        if (base + 1 < B) g_off[base + 1] = off0 + v.x;
        if (base + 2 < B) g_off[base + 2] = off0 + v.x + v.y;
        if (base + 3 < B) g_off[base + 3] = off0 + v.x + v.y + v.z;
    }
    if (bid == 0 && tid == 0) g_off[B] = E;
}

// ---------------- scatter: 8 edges/thread, atomic-free ----------------

__global__ void scatter_kernel(const int* __restrict__ src, int E) {
    const int i = blockIdx.x * blockDim.x + threadIdx.x;
    const int e = i * 8;
    if (e + 7 < E) {
        int4 s0 = ((const int4*)src)[2 * i];
        int4 s1 = ((const int4*)src)[2 * i + 1];
        int4 b0 = ((const int4*)g_bin)[2 * i];
        int4 b1 = ((const int4*)g_bin)[2 * i + 1];
        int4 r0 = ((const int4*)g_rank)[2 * i];
        int4 r1 = ((const int4*)g_rank)[2 * i + 1];
        int p[8];
        p[0] = g_off[b0.x] + r0.x;  p[1] = g_off[b0.y] + r0.y;
        p[2] = g_off[b0.z] + r0.z;  p[3] = g_off[b0.w] + r0.w;
        p[4] = g_off[b1.x] + r1.x;  p[5] = g_off[b1.y] + r1.y;
        p[6] = g_off[b1.z] + r1.z;  p[7] = g_off[b1.w] + r1.w;
        g_packed[p[0]] = s0.x;  g_packed[p[1]] = s0.y;
        g_packed[p[2]] = s0.z;  g_packed[p[3]] = s0.w;
        g_packed[p[4]] = s1.x;  g_packed[p[5]] = s1.y;
        g_packed[p[6]] = s1.z;  g_packed[p[7]] = s1.w;
    } else {
        for (int k = e; k < E; k++)
            g_packed[g_off[g_bin[k]] + g_rank[k]] = src[k];
    }
}

// ------- main: warp per node, per-type segments, fp16 gather, depth-4 -------

__global__ void __launch_bounds__(256)
gcl_main(const float* __restrict__ W,
         const float* __restrict__ Bv,
         float* __restrict__ out, int N)
{
    __shared__ float Wsh[NTYPES][8][8];
    __shared__ float Bsh[NTYPES][8];
    __shared__ float aggS[8][8][16];

    const int tid = threadIdx.x;
    for (int i = tid; i < NTYPES * 64; i += 256) {
        int t = i >> 6, rem = i & 63;
        Wsh[t][rem >> 3][rem & 7] = W[i];
    }
    for (int i = tid; i < NTYPES * 8; i += 256) Bsh[i >> 3][i & 7] = Bv[i];
    __syncthreads();

    const int lane = tid & 31, wl = tid >> 5;
    const int n = blockIdx.x * 8 + wl;
    if (n >= N) return;

    int bnd[NTYPES + 1];
    #pragma unroll
    for (int t = 0; t <= NTYPES; t++) bnd[t] = g_off[n * NTYPES + t];

    const int o  = lane >> 2;
    const int cg = lane & 3;

    float ax = 0.f, ay = 0.f, az = 0.f, aw = 0.f;

    const uint2* __restrict__ xh = (const uint2*)g_xh;  // 4 halves/lane, 256B/node

    #pragma unroll
    for (int t = 0; t < NTYPES; t++) {
        const int lo = bnd[t], hi = bnd[t + 1];
        if (lo == hi) continue;

        float a0 = 0.f, a1 = 0.f, a2 = 0.f, a3 = 0.f;

        int j = lo;
        const int jend = hi - ((hi - lo) & 3);
        if (j < jend) {
            int s0 = g_packed[j],     s1 = g_packed[j + 1];
            int s2 = g_packed[j + 2], s3 = g_packed[j + 3];
            uint2 v0 = xh[(s0 << 5) + lane];
            uint2 v1 = xh[(s1 << 5) + lane];
            uint2 v2 = xh[(s2 << 5) + lane];
            uint2 v3 = xh[(s3 << 5) + lane];
            for (;;) {
                uint2 c0 = v0, c1 = v1, c2 = v2, c3 = v3;
                j += 4;
                if (j < jend) {
                    s0 = g_packed[j];     s1 = g_packed[j + 1];
                    s2 = g_packed[j + 2]; s3 = g_packed[j + 3];
                    v0 = xh[(s0 << 5) + lane];
                    v1 = xh[(s1 << 5) + lane];
                    v2 = xh[(s2 << 5) + lane];
                    v3 = xh[(s3 << 5) + lane];
                }
                #pragma unroll
                for (int q = 0; q < 4; q++) {
                    const uint2 c = (q == 0) ? c0 : (q == 1) ? c1
                                  : (q == 2) ? c2 : c3;
                    float2 f0 = __half22float2(*reinterpret_cast<const __half2*>(&c.x));
                    float2 f1 = __half22float2(*reinterpret_cast<const __half2*>(&c.y));
                    a0 += f0.x; a1 += f0.y; a2 += f1.x; a3 += f1.y;
                }
                if (j >= jend) break;
            }
        }
        for (; j < hi; j++) {
            int s = g_packed[j];
            uint2 v = xh[(s << 5) + lane];
            float2 f0 = __half22float2(*reinterpret_cast<const __half2*>(&v.x));
            float2 f1 = __half22float2(*reinterpret_cast<const __half2*>(&v.y));
            a0 += f0.x; a1 += f0.y; a2 += f1.x; a3 += f1.y;
        }

        // fold this type's aggregate through W[t] via shared transpose
        *(float4*)(&aggS[wl][o][cg * 4]) = make_float4(a0, a1, a2, a3);
        __syncwarp();
        #pragma unroll
        for (int i = 0; i < 8; i++) {
            const float wv = Wsh[t][o][i];
            const float4 a = *(const float4*)(&aggS[wl][i][cg * 4]);
            ax += wv * a.x; ay += wv * a.y; az += wv * a.z; aw += wv * a.w;
        }
        __syncwarp();
    }

    float bias = 0.f;
    #pragma unroll
    for (int t = 0; t < NTYPES; t++)
        bias += (float)(bnd[t + 1] - bnd[t]) * Bsh[t][o];

    float4 res = { ax + bias, ay + bias, az + bias, aw + bias };
    *(float4*)(out + (size_t)n * 128 + o * 16 + cg * 4) = res;
}

// ---------------- launch ----------------

extern "C" void kernel_launch(void* const* d_in, const int* in_sizes, int n_in,
                              void* d_out, int out_size)
{
    const float* x   = (const float*)d_in[0];
    const float* W   = (const float*)d_in[1];
    const float* Bv  = (const float*)d_in[2];
    const int*   src = (const int*)  d_in[3];
    const int*   dst = (const int*)  d_in[4];
    const int*   et  = (const int*)  d_in[5];
    float*       out = (float*)d_out;

    const int E = in_sizes[3];
    const int N = in_sizes[0] / 128;
    const int B = N * NTYPES;
    const int nF4 = N * 32;

    void* cnt_ptr = nullptr;
    cudaGetSymbolAddress(&cnt_ptr, g_cnt);
    cudaMemsetAsync(cnt_ptr, 0, (size_t)B * sizeof(int));

    const int tb = 256;
    const int e8blk = ((E + 7) / 8 + tb - 1) / tb;
    const int cblk  = (nF4 + tb - 1) / tb;

    histcvt_kernel<<<e8blk + cblk, tb>>>(dst, et, x, E, nF4, e8blk);
    scan_lookback<<<(B + SCAN_TILE - 1) / SCAN_TILE, SCAN_BS>>>(B, E);
    scatter_kernel<<<e8blk, tb>>>(src, E);
    gcl_main<<<(N + 7) / 8, 256>>>(W, Bv, out, N);
}